// round 2
// baseline (speedup 1.0000x reference)
#include <cuda_runtime.h>

#define NN 1024
#define HH 128

// Device-global scratch (no allocation allowed)
__device__ float g_agg[NN * HH];
__device__ float g_sr [NN * HH];
__device__ float g_sz [NN * HH];
__device__ float g_sni[NN * HH];
__device__ float g_snh[NN * HH];

// ---------------------------------------------------------------------------
// Kernel 1: agg[i,h] = sum_{j: adj[i,j]!=0} nf[j,h] * T[i,j,h]
// One CTA per i. Compact active-j list in smem (branch-free main loop),
// then 8 warps round-robin the list, 4 entries per iter -> 8 outstanding
// 16B loads per thread. T streamed with __ldcs (evict-first) so nf stays
// L2-resident.
// ---------------------------------------------------------------------------
__global__ __launch_bounds__(256) void agg_kernel(
    const float* __restrict__ nf,
    const int*   __restrict__ adj,
    const float* __restrict__ T)
{
    const int i    = blockIdx.x;
    const int tid  = threadIdx.x;
    const int lane = tid & 31;
    const int w    = tid >> 5;          // 0..7

    __shared__ unsigned short slist[NN];
    __shared__ int scnt;
    __shared__ float4 sred[8][32];

    if (tid == 0) scnt = 0;
    __syncthreads();

    // Compaction: each thread scans 4 adjacency entries, one atomicAdd.
    {
        const int4 a = ((const int4*)(adj + i * NN))[tid];
        int cnt = (a.x != 0) + (a.y != 0) + (a.z != 0) + (a.w != 0);
        int base = atomicAdd(&scnt, cnt);
        int j0 = tid * 4;
        if (a.x) slist[base++] = (unsigned short)(j0);
        if (a.y) slist[base++] = (unsigned short)(j0 + 1);
        if (a.z) slist[base++] = (unsigned short)(j0 + 2);
        if (a.w) slist[base++] = (unsigned short)(j0 + 3);
    }
    __syncthreads();
    const int count = scnt;

    const float4* nf4 = (const float4*)nf;
    const float4* T4  = (const float4*)T;
    const size_t  rowbase = (size_t)i * NN;

    float4 a0 = make_float4(0.f,0.f,0.f,0.f);
    float4 a1 = make_float4(0.f,0.f,0.f,0.f);
    float4 a2 = make_float4(0.f,0.f,0.f,0.f);
    float4 a3 = make_float4(0.f,0.f,0.f,0.f);

    int e = w;
    // Main loop: 4 entries per warp per iter, all loads issued up front.
    for (; e + 24 < count; e += 32) {
        const int j0 = slist[e];
        const int j1 = slist[e + 8];
        const int j2 = slist[e + 16];
        const int j3 = slist[e + 24];
        float4 t0 = __ldcs(&T4[(rowbase + j0) * 32 + lane]);
        float4 t1 = __ldcs(&T4[(rowbase + j1) * 32 + lane]);
        float4 t2 = __ldcs(&T4[(rowbase + j2) * 32 + lane]);
        float4 t3 = __ldcs(&T4[(rowbase + j3) * 32 + lane]);
        float4 f0 = __ldg(&nf4[j0 * 32 + lane]);
        float4 f1 = __ldg(&nf4[j1 * 32 + lane]);
        float4 f2 = __ldg(&nf4[j2 * 32 + lane]);
        float4 f3 = __ldg(&nf4[j3 * 32 + lane]);
        a0.x += f0.x*t0.x; a0.y += f0.y*t0.y; a0.z += f0.z*t0.z; a0.w += f0.w*t0.w;
        a1.x += f1.x*t1.x; a1.y += f1.y*t1.y; a1.z += f1.z*t1.z; a1.w += f1.w*t1.w;
        a2.x += f2.x*t2.x; a2.y += f2.y*t2.y; a2.z += f2.z*t2.z; a2.w += f2.w*t2.w;
        a3.x += f3.x*t3.x; a3.y += f3.y*t3.y; a3.z += f3.z*t3.z; a3.w += f3.w*t3.w;
    }
    // Remainder
    for (; e < count; e += 8) {
        const int j = slist[e];
        float4 t = __ldcs(&T4[(rowbase + j) * 32 + lane]);
        float4 f = __ldg(&nf4[j * 32 + lane]);
        a0.x += f.x*t.x; a0.y += f.y*t.y; a0.z += f.z*t.z; a0.w += f.w*t.w;
    }

    a0.x += a1.x + a2.x + a3.x;
    a0.y += a1.y + a2.y + a3.y;
    a0.z += a1.z + a2.z + a3.z;
    a0.w += a1.w + a2.w + a3.w;

    sred[w][lane] = a0;
    __syncthreads();

    if (tid < 32) {
        float4 s = sred[0][tid];
        #pragma unroll
        for (int ww = 1; ww < 8; ww++) {
            float4 v = sred[ww][tid];
            s.x += v.x; s.y += v.y; s.z += v.z; s.w += v.w;
        }
        ((float4*)g_agg)[i * 32 + tid] = s;
    }
}

// ---------------------------------------------------------------------------
// Kernel 2a: per-gate GEMM partials.
// grid = (NN/8, 3). blockIdx.y = gate g (0=r, 1=z, 2=n).
// block 256: h = tid&127, ty = tid>>7 handles 4 of the 8 rows.
// g<2 -> store gi+gh+biases; g==2 -> store gi_n and gh_n separately.
// ---------------------------------------------------------------------------
__global__ __launch_bounds__(256) void gru_mm_kernel(
    const float* __restrict__ nf,
    const float* __restrict__ wih,
    const float* __restrict__ whh,
    const float* __restrict__ bih,
    const float* __restrict__ bhh)
{
    const int IT  = 8;
    const int ib  = blockIdx.x * IT;
    const int g   = blockIdx.y;
    const int tid = threadIdx.x;
    const int h   = tid & 127;
    const int ty  = tid >> 7;

    __shared__ float4 sA[IT][32];
    __shared__ float4 sH[IT][32];

    #pragma unroll
    for (int e = tid; e < IT * 32; e += 256) {
        int il = e >> 5, k4 = e & 31;
        sA[il][k4] = ((const float4*)g_agg)[(ib + il) * 32 + k4];
        sH[il][k4] = ((const float4*)nf)[(ib + il) * 32 + k4];
    }
    __syncthreads();

    const int row = g * 128 + h;
    const float4* wr = (const float4*)wih + (size_t)row * 32;
    const float4* vr = (const float4*)whh + (size_t)row * 32;

    float ai[4] = {0.f, 0.f, 0.f, 0.f};
    float ah[4] = {0.f, 0.f, 0.f, 0.f};

    #pragma unroll 4
    for (int k4 = 0; k4 < 32; k4++) {
        float4 wv = __ldg(&wr[k4]);
        float4 vv = __ldg(&vr[k4]);
        #pragma unroll
        for (int il = 0; il < 4; il++) {
            const int ii = ty * 4 + il;
            float4 a = sA[ii][k4];
            float4 x = sH[ii][k4];
            ai[il] += a.x*wv.x + a.y*wv.y + a.z*wv.z + a.w*wv.w;
            ah[il] += x.x*vv.x + x.y*vv.y + x.z*vv.z + x.w*vv.w;
        }
    }

    const float bi = bih[row];
    const float bh = bhh[row];

    #pragma unroll
    for (int il = 0; il < 4; il++) {
        const int ii  = ty * 4 + il;
        const int idx = (ib + ii) * 128 + h;
        if (g == 0) {
            g_sr[idx] = ai[il] + ah[il] + bi + bh;
        } else if (g == 1) {
            g_sz[idx] = ai[il] + ah[il] + bi + bh;
        } else {
            g_sni[idx] = ai[il] + bi;
            g_snh[idx] = ah[il] + bh;
        }
    }
}

// ---------------------------------------------------------------------------
// Kernel 2b: elementwise gate fusion.
// ---------------------------------------------------------------------------
__global__ __launch_bounds__(256) void gru_ep_kernel(
    const float* __restrict__ nf,
    float*       __restrict__ out)
{
    const int idx = blockIdx.x * 256 + threadIdx.x;
    float r = 1.f / (1.f + __expf(-g_sr[idx]));
    float z = 1.f / (1.f + __expf(-g_sz[idx]));
    float n = tanhf(g_sni[idx] + r * g_snh[idx]);
    out[idx] = (1.f - z) * n + z * nf[idx];
}

extern "C" void kernel_launch(void* const* d_in, const int* in_sizes, int n_in,
                              void* d_out, int out_size)
{
    const float* nf  = (const float*)d_in[0];
    const int*   adj = (const int*)  d_in[1];
    const float* T   = (const float*)d_in[2];
    const float* wih = (const float*)d_in[3];
    const float* whh = (const float*)d_in[4];
    const float* bih = (const float*)d_in[5];
    const float* bhh = (const float*)d_in[6];
    float* out = (float*)d_out;

    agg_kernel<<<NN, 256>>>(nf, adj, T);
    gru_mm_kernel<<<dim3(NN / 8, 3), 256>>>(nf, wih, whh, bih, bhh);
    gru_ep_kernel<<<(NN * HH) / 256, 256>>>(nf, out);
}